// round 11
// baseline (speedup 1.0000x reference)
#include <cuda_runtime.h>
#include <cfloat>
#include <math.h>

// Edge lists for the two MSTs (max n = 4096 -> 4095 edges each).
#define NMAX 4096
__device__ int2 g_edges[2][NMAX];

// ---------------------------------------------------------------------------
// Pre-kernel: pull both matrices into L2 (~126 MB L2 vs 128 MB data).
// Measured: ~13 us @ 5.9 TB/s.
// ---------------------------------------------------------------------------
__global__ void prefetch_kernel(const float* __restrict__ d1,
                                const float* __restrict__ d2,
                                int n)
{
    const size_t total = (size_t)n * n;
    const int nb = gridDim.x >> 1;
    const float* __restrict__ m = (blockIdx.x < nb) ? d1 : d2;
    const int b = blockIdx.x % nb;

    const size_t chunk = (total + nb - 1) / nb;
    const size_t start = (size_t)b * chunk;
    const size_t end   = (start + chunk < total) ? start + chunk : total;

    for (size_t off = start + (size_t)threadIdx.x * 32;
         off < end;
         off += (size_t)blockDim.x * 32) {
        asm volatile("prefetch.global.L2 [%0];" :: "l"(m + off));
    }
}

// ---------------------------------------------------------------------------
// Prim's MST, bit-exact vs reference (strict-< relax, FLT_MAX masking,
// argmin tie-break to lowest index). One block per matrix, 1024 threads,
// 4 owned elements per thread.
//
// Load shape (critical, per R1/R5/R9 evidence): exactly ONE lane-contiguous
// float4 per thread -> each warp-level LDG.128 touches 4 x 128B lines, the
// minimum; 128 L1tex wavefronts per 16KB row (the floor). Multi-float4-per-
// thread layouts cost 2-4x more wavefronts and regressed.
//
// Reduction shape: warp argmin = two dependent 32-bit REDUX.MIN; 32 warp
// leaders publish packed (valuebits<<32|idx) u64 to double-buffered smem;
// ONE __syncthreads; every thread redundantly tree-mins the 32 broadcast
// entries (depth-5 register tree) -> no second cascade, no second barrier.
//
// All register-array indexing is compile-time (unrolled/predicated) -> no
// local-memory spills.
// ---------------------------------------------------------------------------
__global__ __launch_bounds__(1024, 1)
void mst_kernel(const float* __restrict__ d1,
                const float* __restrict__ d2,
                int n)
{
    const float* __restrict__ d = (blockIdx.x == 0) ? d1 : d2;
    int2* edges = g_edges[blockIdx.x];

    const int tid  = threadIdx.x;
    const int lane = tid & 31;
    const int wid  = tid >> 5;
    const int base = tid << 2;            // first of 4 owned indices

    __shared__ unsigned long long wbest[2][32];

    // ---- init: min_dist = d[0,:], parent = 0, node 0 in tree ----
    float md[4];
    int   par[4];
    {
        const float4 a = reinterpret_cast<const float4*>(d)[tid];
        md[0] = a.x; md[1] = a.y; md[2] = a.z; md[3] = a.w;
    }
    par[0] = par[1] = par[2] = par[3] = 0;
    if (tid == 0) md[0] = FLT_MAX;        // node 0 already in tree

    // packed key: (float bits << 32) | index — min() => lowest value, then
    // lowest index (== jnp.argmin tie-break); bits order-preserving for >=0.
    #define PKEY(K) ((((unsigned long long)__float_as_uint(md[K])) << 32) \
                     | (unsigned)(base + (K)))

    unsigned long long lkey;
    {
        const unsigned long long k0 = min(PKEY(0), PKEY(1));
        const unsigned long long k1 = min(PKEY(2), PKEY(3));
        lkey = min(k0, k1);
    }

    int buf = 0;
    for (int it = 0; it < n - 1; ++it) {
        // ---- warp argmin: two dependent 32-bit hardware reductions ----
        const unsigned lv   = (unsigned)(lkey >> 32);
        const unsigned vmin = __reduce_min_sync(0xffffffffu, lv);
        const unsigned cand = (lv == vmin) ? (unsigned)lkey : 0xFFFFFFFFu;
        const unsigned imin = __reduce_min_sync(0xffffffffu, cand);
        if (lane == 0)
            wbest[buf][wid] = (((unsigned long long)vmin) << 32) | imin;
        __syncthreads();

        // ---- block argmin: every thread tree-mins 32 broadcast entries ----
        const unsigned long long* wb = wbest[buf];
        unsigned long long a0 = min(wb[0],  wb[1]);
        unsigned long long a1 = min(wb[2],  wb[3]);
        unsigned long long a2 = min(wb[4],  wb[5]);
        unsigned long long a3 = min(wb[6],  wb[7]);
        unsigned long long a4 = min(wb[8],  wb[9]);
        unsigned long long a5 = min(wb[10], wb[11]);
        unsigned long long a6 = min(wb[12], wb[13]);
        unsigned long long a7 = min(wb[14], wb[15]);
        unsigned long long b0 = min(wb[16], wb[17]);
        unsigned long long b1 = min(wb[18], wb[19]);
        unsigned long long b2 = min(wb[20], wb[21]);
        unsigned long long b3 = min(wb[22], wb[23]);
        unsigned long long b4 = min(wb[24], wb[25]);
        unsigned long long b5 = min(wb[26], wb[27]);
        unsigned long long b6 = min(wb[28], wb[29]);
        unsigned long long b7 = min(wb[30], wb[31]);
        a0 = min(a0, a1); a2 = min(a2, a3); a4 = min(a4, a5); a6 = min(a6, a7);
        b0 = min(b0, b1); b2 = min(b2, b3); b4 = min(b4, b5); b6 = min(b6, b7);
        a0 = min(a0, a2); a4 = min(a4, a6); b0 = min(b0, b2); b4 = min(b4, b6);
        const unsigned long long bb = min(min(a0, a4), min(b0, b4));
        const int j = (int)(unsigned)bb;   // low word = global argmin index

        // ---- row load ASAP: ONE lane-contiguous float4 per thread
        //      (minimum-wavefront shape); evict-first, row is dead after. ----
        const float4 v =
            __ldcs(reinterpret_cast<const float4*>(d + (size_t)j * n) + tid);

        // ---- owner records edge (parent BEFORE relax), marks j in-tree.
        //      Static indices only -> stays in registers. ----
        if ((j >> 2) == tid) {
            const int jj = j & 3;
            #pragma unroll
            for (int k = 0; k < 4; ++k) {
                if (jj == k) {
                    edges[it] = make_int2(par[k], j);
                    md[k] = FLT_MAX;
                }
            }
        }

        // ---- relax (strict <, skip in-tree) + local argmin ----
        const float vv[4] = { v.x, v.y, v.z, v.w };
        #pragma unroll
        for (int k = 0; k < 4; ++k) {
            if (md[k] != FLT_MAX && vv[k] < md[k]) {
                md[k]  = vv[k];
                par[k] = j;
            }
        }
        {
            const unsigned long long k0 = min(PKEY(0), PKEY(1));
            const unsigned long long k1 = min(PKEY(2), PKEY(3));
            lkey = min(k0, k1);
        }

        buf ^= 1;
    }
    #undef PKEY
}

// ---------------------------------------------------------------------------
// Gather both signatures and reduce:
//   result = sum_{e in p1}(d1[e]-d2[e])^2 + sum_{e in p2}(d1[e]-d2[e])^2
// ---------------------------------------------------------------------------
__global__ __launch_bounds__(1024, 1)
void finalize_kernel(const float* __restrict__ d1,
                     const float* __restrict__ d2,
                     float* __restrict__ out,
                     int n)
{
    __shared__ float warp_sums[32];
    const int tid = threadIdx.x;

    float acc = 0.0f;
    for (int i = tid; i < n - 1; i += blockDim.x) {
        int2 e1 = g_edges[0][i];
        int2 e2 = g_edges[1][i];
        size_t o1 = (size_t)e1.x * n + e1.y;
        size_t o2 = (size_t)e2.x * n + e2.y;
        float a = d1[o1] - d2[o1];
        float b = d1[o2] - d2[o2];
        acc += a * a + b * b;
    }
    #pragma unroll
    for (int o = 16; o; o >>= 1)
        acc += __shfl_xor_sync(0xffffffffu, acc, o);
    if ((tid & 31) == 0) warp_sums[tid >> 5] = acc;
    __syncthreads();
    if (tid < 32) {
        float v = (tid < (int)(blockDim.x >> 5)) ? warp_sums[tid] : 0.0f;
        #pragma unroll
        for (int o = 16; o; o >>= 1)
            v += __shfl_xor_sync(0xffffffffu, v, o);
        if (tid == 0) out[0] = v;
    }
}

extern "C" void kernel_launch(void* const* d_in, const int* in_sizes, int n_in,
                              void* d_out, int out_size)
{
    const float* d1 = (const float*)d_in[0];
    const float* d2 = (const float*)d_in[1];
    float* out = (float*)d_out;

    const int n = (int)lrint(sqrt((double)in_sizes[0]));   // 4096

    prefetch_kernel<<<64, 1024>>>(d1, d2, n);
    mst_kernel<<<2, 1024>>>(d1, d2, n);
    finalize_kernel<<<1, 1024>>>(d1, d2, out, n);
}

// round 12
// speedup vs baseline: 1.6824x; 1.6824x over previous
#include <cuda_runtime.h>
#include <cfloat>
#include <math.h>

// Edge lists for the two MSTs (max n = 4096 -> 4095 edges each).
#define NMAX 4096
__device__ int2 g_edges[2][NMAX];

// ---------------------------------------------------------------------------
// Pre-kernel: pull both matrices into L2 (~126 MB L2 vs 128 MB data).
// Measured: ~13 us @ 5.6-5.9 TB/s.
// ---------------------------------------------------------------------------
__global__ void prefetch_kernel(const float* __restrict__ d1,
                                const float* __restrict__ d2,
                                int n)
{
    const size_t total = (size_t)n * n;
    const int nb = gridDim.x >> 1;
    const float* __restrict__ m = (blockIdx.x < nb) ? d1 : d2;
    const int b = blockIdx.x % nb;

    const size_t chunk = (total + nb - 1) / nb;
    const size_t start = (size_t)b * chunk;
    const size_t end   = (start + chunk < total) ? start + chunk : total;

    for (size_t off = start + (size_t)threadIdx.x * 32;
         off < end;
         off += (size_t)blockDim.x * 32) {
        asm volatile("prefetch.global.L2 [%0];" :: "l"(m + off));
    }
}

// ---------------------------------------------------------------------------
// Prim's MST, bit-exact vs the reference (strict-< relax, sentinel masking,
// argmin tie-break to lowest index).
//
// One block of 128 threads (4 warps) per matrix; 32 elements per thread in
// registers, interleaved mapping: chunk q (0..7), thread t owns elements
// 512*q + 4*t + c (c=0..3) == float4 index q*128+t of the row.
//   -> warp-level LDG.128s are lane-consecutive: 4 lines per LDG,
//      8*4*4 = 128 L1tex wavefronts per row (the floor).
//
// In-tree sentinel = quiet NaN: relax's (v < md) is false against NaN (no
// explicit guard needed) and NaN's bit pattern sorts above every finite
// float in the packed (bits<<32 | idx) argmin key -- semantically identical
// to the reference's finfo.max masking (all real distances finite).
//
// Local argmin is maintained INCREMENTALLY: lkey folds a new key only on a
// successful relax; a full 32-element rebuild happens only on the single
// thread whose own argmin element was just removed.
//
// Global argmin: 2x 32-bit REDUX warp reduction, 4 leaders -> smem (double
// buffered), ONE __syncthreads, every thread mins 4 u64 entries.
// ---------------------------------------------------------------------------
__global__ __launch_bounds__(128, 1)
void mst_kernel(const float* __restrict__ d1,
                const float* __restrict__ d2,
                int n)
{
    const float* __restrict__ d = (blockIdx.x == 0) ? d1 : d2;
    int2* edges = g_edges[blockIdx.x];

    const int tid  = threadIdx.x;
    const int lane = tid & 31;
    const int wid  = tid >> 5;

    __shared__ unsigned long long wbest[2][4];

    const float SENT = __int_as_float(0x7FC00000);   // quiet NaN sentinel

    float md[8][4];
    int   par[8][4];

    // ---- init: min_dist = d[0,:], parent = 0, node 0 in tree ----
    {
        const float4* row0 = reinterpret_cast<const float4*>(d);
        #pragma unroll
        for (int q = 0; q < 8; ++q) {
            const float4 a = row0[q * 128 + tid];
            md[q][0] = a.x; md[q][1] = a.y; md[q][2] = a.z; md[q][3] = a.w;
            par[q][0] = par[q][1] = par[q][2] = par[q][3] = 0;
        }
    }
    if (tid == 0) md[0][0] = SENT;        // node 0 already in tree

    // packed key: (float bits << 32) | element index. min() => lowest value,
    // then lowest index (== jnp.argmin tie-break); bits order-preserving >=0.
    #define PKEY(Q, C) ((((unsigned long long)__float_as_uint(md[Q][C])) << 32) \
                        | (unsigned)(512 * (Q) + 4 * tid + (C)))

    #define FULL_ARGMIN(OUT) do {                                   \
        unsigned long long t_[8];                                   \
        _Pragma("unroll")                                           \
        for (int q_ = 0; q_ < 8; ++q_) {                            \
            unsigned long long u0 = min(PKEY(q_, 0), PKEY(q_, 1));  \
            unsigned long long u1 = min(PKEY(q_, 2), PKEY(q_, 3));  \
            t_[q_] = min(u0, u1);                                   \
        }                                                           \
        t_[0] = min(t_[0], t_[1]); t_[2] = min(t_[2], t_[3]);       \
        t_[4] = min(t_[4], t_[5]); t_[6] = min(t_[6], t_[7]);       \
        (OUT) = min(min(t_[0], t_[2]), min(t_[4], t_[6]));          \
    } while (0)

    unsigned long long lkey;
    FULL_ARGMIN(lkey);

    int buf = 0;
    for (int it = 0; it < n - 1; ++it) {
        // ---- warp argmin: two dependent 32-bit hardware reductions ----
        const unsigned lv   = (unsigned)(lkey >> 32);
        const unsigned vmin = __reduce_min_sync(0xffffffffu, lv);
        const unsigned cand = (lv == vmin) ? (unsigned)lkey : 0xFFFFFFFFu;
        const unsigned imin = __reduce_min_sync(0xffffffffu, cand);
        if (lane == 0)
            wbest[buf][wid] = (((unsigned long long)vmin) << 32) | imin;
        __syncthreads();

        // ---- block argmin: min of 4 broadcast entries ----
        const unsigned long long bb =
            min(min(wbest[buf][0], wbest[buf][1]),
                min(wbest[buf][2], wbest[buf][3]));
        const int j = (int)(unsigned)bb;

        // ---- row load ASAP: 8 lane-consecutive float4 LDGs (MLP=8,
        //      4 lines each -> 128 wavefronts total, the floor) ----
        const float4* row =
            reinterpret_cast<const float4*>(d + (size_t)j * n);
        float4 v[8];
        #pragma unroll
        for (int q = 0; q < 8; ++q) v[q] = row[q * 128 + tid];

        // ---- owner records edge (parent BEFORE relax), marks j in-tree ----
        bool need_full = false;
        if (((j >> 2) & 127) == tid) {
            const int qj = j >> 9;
            const int cj = j & 3;
            #pragma unroll
            for (int q = 0; q < 8; ++q)
                #pragma unroll
                for (int c = 0; c < 4; ++c)
                    if (qj == q && cj == c) {
                        edges[it] = make_int2(par[q][c], j);
                        md[q][c] = SENT;
                    }
            need_full = ((unsigned)lkey == (unsigned)j);
        }

        // ---- relax: (v < md) is false vs NaN sentinel -> no guard.
        //      Fold lkey incrementally on success (rare). ----
        #pragma unroll
        for (int q = 0; q < 8; ++q) {
            const float x[4] = { v[q].x, v[q].y, v[q].z, v[q].w };
            #pragma unroll
            for (int c = 0; c < 4; ++c) {
                if (x[c] < md[q][c]) {
                    md[q][c]  = x[c];
                    par[q][c] = j;
                    lkey = min(lkey, PKEY(q, c));
                }
            }
        }

        // ---- only the thread whose own argmin was removed rebuilds ----
        if (need_full) FULL_ARGMIN(lkey);

        buf ^= 1;
    }
    #undef FULL_ARGMIN
    #undef PKEY
}

// ---------------------------------------------------------------------------
// Gather both signatures and reduce:
//   result = sum_{e in p1}(d1[e]-d2[e])^2 + sum_{e in p2}(d1[e]-d2[e])^2
// ---------------------------------------------------------------------------
__global__ __launch_bounds__(1024, 1)
void finalize_kernel(const float* __restrict__ d1,
                     const float* __restrict__ d2,
                     float* __restrict__ out,
                     int n)
{
    __shared__ float warp_sums[32];
    const int tid = threadIdx.x;

    float acc = 0.0f;
    for (int i = tid; i < n - 1; i += blockDim.x) {
        int2 e1 = g_edges[0][i];
        int2 e2 = g_edges[1][i];
        size_t o1 = (size_t)e1.x * n + e1.y;
        size_t o2 = (size_t)e2.x * n + e2.y;
        float a = d1[o1] - d2[o1];
        float b = d1[o2] - d2[o2];
        acc += a * a + b * b;
    }
    #pragma unroll
    for (int o = 16; o; o >>= 1)
        acc += __shfl_xor_sync(0xffffffffu, acc, o);
    if ((tid & 31) == 0) warp_sums[tid >> 5] = acc;
    __syncthreads();
    if (tid < 32) {
        float v = (tid < (int)(blockDim.x >> 5)) ? warp_sums[tid] : 0.0f;
        #pragma unroll
        for (int o = 16; o; o >>= 1)
            v += __shfl_xor_sync(0xffffffffu, v, o);
        if (tid == 0) out[0] = v;
    }
}

extern "C" void kernel_launch(void* const* d_in, const int* in_sizes, int n_in,
                              void* d_out, int out_size)
{
    const float* d1 = (const float*)d_in[0];
    const float* d2 = (const float*)d_in[1];
    float* out = (float*)d_out;

    const int n = (int)lrint(sqrt((double)in_sizes[0]));   // 4096

    prefetch_kernel<<<64, 1024>>>(d1, d2, n);
    mst_kernel<<<2, 128>>>(d1, d2, n);
    finalize_kernel<<<1, 1024>>>(d1, d2, out, n);
}

// round 15
// speedup vs baseline: 13.5165x; 8.0342x over previous
#include <cuda_runtime.h>
#include <cfloat>
#include <math.h>

#define NMAX 4096
#define SB   64            // scan blocks per matrix

// Per-matrix state (m = 0,1)
__device__ int                g_comp [2][NMAX];   // component root per vertex
__device__ unsigned long long g_vbest[2][NMAX];   // cached best outgoing edge key per vertex
__device__ unsigned long long g_cbest[2][NMAX];   // best outgoing edge key per root
__device__ int2               g_edges[2][NMAX];   // MST edges (unordered pairs)
__device__ int                g_ecnt [2];
__device__ int                g_ncomp[2];

// Key layout (56 bits): fp32 bits of d (order-preserving, d >= 0 finite) << 24
//                       | min(i,j) << 12 | max(i,j).
// Order-invariant in (i,j) -> both endpoint components of one physical edge
// compute the IDENTICAL key, so "mutual minimum" == key equality, and keys
// are globally distinct per pair -> cycle-free hooking, unique tie-broken MST.
#define KEY_INF 0xFFFFFFFFFFFFFFFFull

__device__ __forceinline__ unsigned long long pack_key(float w, int i, int j) {
    const unsigned mn = min(i, j), mx = max(i, j);
    return (((unsigned long long)__float_as_uint(w)) << 24)
         | ((unsigned long long)mn << 12) | (unsigned long long)mx;
}

// ---------------------------------------------------------------------------
__global__ void init_kernel(int n)
{
    const int m = blockIdx.y;
    const int i = blockIdx.x * blockDim.x + threadIdx.x;
    if (i < n) {
        g_comp [m][i] = i;
        g_cbest[m][i] = KEY_INF;
        g_vbest[m][i] = KEY_INF;
        // Deterministic edge buffer contents even if a logic bug under-fills.
        g_edges[m][i] = make_int2(0, 0);
    }
    if (i == 0) { g_ecnt[m] = 0; g_ncomp[m] = n; }
}

// ---------------------------------------------------------------------------
// Scan: per vertex, maintain its best outgoing edge (to another component).
// Cached vbest stays optimal while its target is still external (candidate
// set only shrinks); otherwise the block cooperatively rescans the row.
// Valid/rescanned bests are atomicMin'ed into the owning root's g_cbest.
// grid = 2*SB blocks, 256 threads. blockIdx & 1 = matrix.
// ---------------------------------------------------------------------------
__global__ __launch_bounds__(256, 1)
void scan_kernel(const float* __restrict__ d1,
                 const float* __restrict__ d2,
                 int n, int round)
{
    const int m = blockIdx.x & 1;
    if (g_ncomp[m] <= 1) return;
    const float* __restrict__ d = (m == 0) ? d1 : d2;
    const int b = blockIdx.x >> 1;

    __shared__ __align__(16) int comp_s[NMAX];
    __shared__ int queue[SB];
    __shared__ int qcnt;
    __shared__ unsigned long long wred[8];

    const int tid  = threadIdx.x;
    const int lane = tid & 31;

    for (int i = tid; i < n; i += 256) comp_s[i] = g_comp[m][i];
    if (tid == 0) qcnt = 0;
    __syncthreads();

    // ---- phase 1: validity check of cached bests; queue invalidated ones ----
    const int vpb = n / SB;                 // 64 vertices per block
    const int v0  = b * vpb;
    for (int i = v0 + tid; i < v0 + vpb; i += 256) {
        bool need = true;
        if (round > 0) {
            const unsigned long long key = g_vbest[m][i];
            if (key != KEY_INF) {
                const int mn = (int)((key >> 12) & 0xFFF);
                const int mx = (int)(key & 0xFFF);
                const int t  = (mn == i) ? mx : mn;
                if (comp_s[t] != comp_s[i]) {  // still crossing -> still optimal
                    need = false;
                    atomicMin(&g_cbest[m][comp_s[i]], key);
                }
            }
        }
        if (need) {
            const int slot = atomicAdd(&qcnt, 1);
            if (slot < SB) queue[slot] = i;
        }
    }
    __syncthreads();

    // ---- phase 2: cooperative full-row rescan for queued vertices ----
    const int nq = min(qcnt, SB);
    const int nf4 = n >> 2;                 // float4s per row (1024)
    for (int q = 0; q < nq; ++q) {
        const int i  = queue[q];
        const int ci = comp_s[i];
        const float4* __restrict__ row =
            reinterpret_cast<const float4*>(d + (size_t)i * n);
        const int4* __restrict__ c4p = reinterpret_cast<const int4*>(comp_s);

        unsigned long long best = KEY_INF;
        for (int f4 = tid; f4 < nf4; f4 += 256) {
            const float4 w = row[f4];
            const int4  cc = c4p[f4];
            const int j0 = f4 << 2;
            if (cc.x != ci) best = min(best, pack_key(w.x, i, j0 + 0));
            if (cc.y != ci) best = min(best, pack_key(w.y, i, j0 + 1));
            if (cc.z != ci) best = min(best, pack_key(w.z, i, j0 + 2));
            if (cc.w != ci) best = min(best, pack_key(w.w, i, j0 + 3));
        }
        #pragma unroll
        for (int o = 16; o; o >>= 1)
            best = min(best, __shfl_xor_sync(0xffffffffu, best, o));
        if (lane == 0) wred[tid >> 5] = best;
        __syncthreads();
        if (tid == 0) {
            unsigned long long bb =
                min(min(min(wred[0], wred[1]), min(wred[2], wred[3])),
                    min(min(wred[4], wred[5]), min(wred[6], wred[7])));
            g_vbest[m][i] = bb;
            if (bb != KEY_INF) atomicMin(&g_cbest[m][ci], bb);
        }
        __syncthreads();
    }
}

// ---------------------------------------------------------------------------
// Merge: each live root hooks along its min outgoing edge; mutual pairs
// (identical keys) merge once with the smaller root surviving. smem pointer
// jumping fully compresses, comp[] is rewritten to final roots, components
// recounted, cbest reset. One block per matrix, 1024 threads.
// ---------------------------------------------------------------------------
__global__ __launch_bounds__(1024, 1)
void merge_kernel(int n)
{
    const int m = blockIdx.x;
    if (g_ncomp[m] <= 1) return;

    __shared__ int par_s[NMAX];
    __shared__ int nroots;
    const int tid = threadIdx.x;

    if (tid == 0) nroots = 0;
    for (int c = tid; c < n; c += 1024) par_s[c] = c;
    __syncthreads();

    // hooking + edge emission
    for (int c = tid; c < n; c += 1024) {
        const unsigned long long key = g_cbest[m][c];
        if (key != KEY_INF) {                       // c is a live root
            const int mn = (int)((key >> 12) & 0xFFF);
            const int mx = (int)(key & 0xFFF);
            const int ru = g_comp[m][mn];
            const int rv = g_comp[m][mx];
            const int t  = (ru == c) ? rv : ru;     // the other root
            const bool mutual = (g_cbest[m][t] == key);
            if (!mutual || c < t) {                 // mutual: smaller emits
                const int e = atomicAdd(&g_ecnt[m], 1);
                if (e < n - 1)                      // hardened: never OOB
                    g_edges[m][e] = make_int2(mn, mx);
            }
            par_s[c] = (mutual && c < t) ? c : t;
        }
    }
    __syncthreads();

    // pointer jumping (12 doublings cover depth 4096)
    #pragma unroll
    for (int p = 0; p < 12; ++p) {
        for (int c = tid; c < n; c += 1024) par_s[c] = par_s[par_s[c]];
        __syncthreads();
    }

    // rewrite comp to final roots
    for (int i = tid; i < n; i += 1024)
        g_comp[m][i] = par_s[g_comp[m][i]];

    // recount live roots; reset cbest for next round
    for (int c = tid; c < n; c += 1024) {
        if (g_cbest[m][c] != KEY_INF && par_s[c] == c) atomicAdd(&nroots, 1);
        g_cbest[m][c] = KEY_INF;
    }
    __syncthreads();
    if (tid == 0) g_ncomp[m] = nroots;
}

// ---------------------------------------------------------------------------
// result = sum_{e in T1}(d1[e]-d2[e])^2 + sum_{e in T2}(d1[e]-d2[e])^2
// (edge order arbitrary; matrices symmetric -> orientation irrelevant)
// ---------------------------------------------------------------------------
__global__ __launch_bounds__(1024, 1)
void finalize_kernel(const float* __restrict__ d1,
                     const float* __restrict__ d2,
                     float* __restrict__ out,
                     int n)
{
    __shared__ float warp_sums[32];
    const int tid = threadIdx.x;

    float acc = 0.0f;
    for (int i = tid; i < n - 1; i += blockDim.x) {
        const int2 e1 = g_edges[0][i];
        const int2 e2 = g_edges[1][i];
        const size_t o1 = (size_t)e1.x * n + e1.y;
        const size_t o2 = (size_t)e2.x * n + e2.y;
        const float a = d1[o1] - d2[o1];
        const float b = d1[o2] - d2[o2];
        acc += a * a + b * b;
    }
    #pragma unroll
    for (int o = 16; o; o >>= 1)
        acc += __shfl_xor_sync(0xffffffffu, acc, o);
    if ((tid & 31) == 0) warp_sums[tid >> 5] = acc;
    __syncthreads();
    if (tid < 32) {
        float v = (tid < (int)(blockDim.x >> 5)) ? warp_sums[tid] : 0.0f;
        #pragma unroll
        for (int o = 16; o; o >>= 1)
            v += __shfl_xor_sync(0xffffffffu, v, o);
        if (tid == 0) out[0] = v;
    }
}

extern "C" void kernel_launch(void* const* d_in, const int* in_sizes, int n_in,
                              void* d_out, int out_size)
{
    const float* d1 = (const float*)d_in[0];
    const float* d2 = (const float*)d_in[1];
    float* out = (float*)d_out;

    const int n = (int)lrint(sqrt((double)in_sizes[0]));   // 4096

    init_kernel<<<dim3((n + 1023) / 1024, 2), 1024>>>(n);

    // Boruvka: components at least halve per round -> 12 rounds suffice for
    // n=4096. Dead rounds early-exit on g_ncomp (cheap graph nodes).
    for (int r = 0; r < 12; ++r) {
        scan_kernel<<<2 * SB, 256>>>(d1, d2, n, r);
        merge_kernel<<<2, 1024>>>(n);
    }

    finalize_kernel<<<1, 1024>>>(d1, d2, out, n);
}

// round 16
// speedup vs baseline: 28.3567x; 2.0979x over previous
#include <cuda_runtime.h>
#include <cfloat>
#include <math.h>

#define NMAX 4096
#define SB   128           // cached-scan blocks per matrix (32 vertices each)

// Per-matrix state (m = 0,1)
__device__ int                g_comp [2][NMAX];   // component root per vertex
__device__ unsigned long long g_vbest[2][NMAX];   // cached best outgoing edge key per vertex
__device__ unsigned long long g_cbest[2][NMAX];   // best outgoing edge key per root
__device__ int2               g_edges[2][NMAX];   // MST edges (unordered pairs)
__device__ int                g_ecnt [2];
__device__ int                g_ncomp[2];

// Key layout (56 bits): fp32 bits of d (order-preserving, d >= 0 finite) << 24
//                       | min(i,j) << 12 | max(i,j).
// Order-invariant in (i,j) -> both endpoint components of one physical edge
// compute the IDENTICAL key, so "mutual minimum" == key equality, and keys
// are globally distinct per pair -> cycle-free hooking, unique tie-broken MST.
#define KEY_INF 0xFFFFFFFFFFFFFFFFull

__device__ __forceinline__ unsigned long long pack_key(float w, int i, int j) {
    const unsigned mn = min(i, j), mx = max(i, j);
    return (((unsigned long long)__float_as_uint(w)) << 24)
         | ((unsigned long long)mn << 12) | (unsigned long long)mx;
}

// ---------------------------------------------------------------------------
__global__ void init_kernel(int n)
{
    const int m = blockIdx.y;
    const int i = blockIdx.x * blockDim.x + threadIdx.x;
    if (i < n) {
        g_comp [m][i] = i;
        g_cbest[m][i] = KEY_INF;
        g_vbest[m][i] = KEY_INF;
        g_edges[m][i] = make_int2(0, 0);
    }
    if (i == 0) { g_ecnt[m] = 0; g_ncomp[m] = n; }
}

// ---------------------------------------------------------------------------
// Round 0 scan: every vertex is its own component, so every j != i crosses.
// One WARP per row, streaming: lanes stride the row, shfl-reduce, lane 0
// writes vbest and cbest directly (root == i; no atomic needed).
// grid = (n/8, 2), 256 threads (8 warps/block). Pure 128 MB stream.
// ---------------------------------------------------------------------------
__global__ __launch_bounds__(256, 1)
void scan0_kernel(const float* __restrict__ d1,
                  const float* __restrict__ d2,
                  int n)
{
    const int m = blockIdx.y;
    const float* __restrict__ d = (m == 0) ? d1 : d2;
    const int i    = blockIdx.x * 8 + (threadIdx.x >> 5);   // row
    const int lane = threadIdx.x & 31;

    const float4* __restrict__ row =
        reinterpret_cast<const float4*>(d + (size_t)i * n);
    const int nf4 = n >> 2;

    unsigned long long best = KEY_INF;
    for (int f4 = lane; f4 < nf4; f4 += 32) {
        const float4 w = row[f4];
        const int j0 = f4 << 2;
        if (j0 + 0 != i) best = min(best, pack_key(w.x, i, j0 + 0));
        if (j0 + 1 != i) best = min(best, pack_key(w.y, i, j0 + 1));
        if (j0 + 2 != i) best = min(best, pack_key(w.z, i, j0 + 2));
        if (j0 + 3 != i) best = min(best, pack_key(w.w, i, j0 + 3));
    }
    #pragma unroll
    for (int o = 16; o; o >>= 1)
        best = min(best, __shfl_xor_sync(0xffffffffu, best, o));
    if (lane == 0) {
        g_vbest[m][i] = best;
        g_cbest[m][i] = best;     // comp[i] == i in round 0
    }
}

// ---------------------------------------------------------------------------
// Cached scan (rounds >= 1): per vertex, cached best stays optimal while its
// target is still external (candidate set only shrinks); invalidated vertices
// are queued and rescanned WARP-PER-VERTEX (8 concurrent rows, no in-loop
// barriers). Bests are atomicMin'ed into the owning root's g_cbest.
// grid = 2*SB blocks, 256 threads; 32 vertices per block.
// ---------------------------------------------------------------------------
__global__ __launch_bounds__(256, 1)
void scan_kernel(const float* __restrict__ d1,
                 const float* __restrict__ d2,
                 int n)
{
    const int m = blockIdx.x & 1;
    if (g_ncomp[m] <= 1) return;
    const float* __restrict__ d = (m == 0) ? d1 : d2;
    const int b = blockIdx.x >> 1;

    __shared__ __align__(16) int comp_s[NMAX];
    __shared__ int queue[NMAX / SB];
    __shared__ int qcnt;

    const int tid  = threadIdx.x;
    const int lane = tid & 31;
    const int wid  = tid >> 5;

    for (int i = tid; i < n; i += 256) comp_s[i] = g_comp[m][i];
    if (tid == 0) qcnt = 0;
    __syncthreads();

    // ---- phase 1: validity check of cached bests; queue invalidated ones ----
    const int vpb = n / SB;                 // 32 vertices per block
    const int v0  = b * vpb;
    for (int i = v0 + tid; i < v0 + vpb; i += 256) {
        bool need = true;
        const unsigned long long key = g_vbest[m][i];
        if (key != KEY_INF) {
            const int mn = (int)((key >> 12) & 0xFFF);
            const int mx = (int)(key & 0xFFF);
            const int t  = (mn == i) ? mx : mn;
            if (comp_s[t] != comp_s[i]) {   // still crossing -> still optimal
                need = false;
                atomicMin(&g_cbest[m][comp_s[i]], key);
            }
        }
        if (need) {
            const int slot = atomicAdd(&qcnt, 1);
            if (slot < vpb) queue[slot] = i;
        }
    }
    __syncthreads();

    // ---- phase 2: warp-per-vertex full-row rescan (8 concurrent rows) ----
    const int nq  = min(qcnt, vpb);
    const int nf4 = n >> 2;
    for (int q = wid; q < nq; q += 8) {
        const int i  = queue[q];
        const int ci = comp_s[i];
        const float4* __restrict__ row =
            reinterpret_cast<const float4*>(d + (size_t)i * n);
        const int4* __restrict__ c4p = reinterpret_cast<const int4*>(comp_s);

        unsigned long long best = KEY_INF;
        for (int f4 = lane; f4 < nf4; f4 += 32) {
            const float4 w = row[f4];
            const int4  cc = c4p[f4];
            const int j0 = f4 << 2;
            if (cc.x != ci) best = min(best, pack_key(w.x, i, j0 + 0));
            if (cc.y != ci) best = min(best, pack_key(w.y, i, j0 + 1));
            if (cc.z != ci) best = min(best, pack_key(w.z, i, j0 + 2));
            if (cc.w != ci) best = min(best, pack_key(w.w, i, j0 + 3));
        }
        #pragma unroll
        for (int o = 16; o; o >>= 1)
            best = min(best, __shfl_xor_sync(0xffffffffu, best, o));
        if (lane == 0) {
            g_vbest[m][i] = best;
            if (best != KEY_INF) atomicMin(&g_cbest[m][ci], best);
        }
    }
}

// ---------------------------------------------------------------------------
// Merge: each live root hooks along its min outgoing edge; mutual pairs
// (identical keys) merge once with the smaller root surviving. smem pointer
// jumping fully compresses, comp[] rewritten, components recounted, cbest
// reset. One block per matrix, 1024 threads.
// ---------------------------------------------------------------------------
__global__ __launch_bounds__(1024, 1)
void merge_kernel(int n)
{
    const int m = blockIdx.x;
    if (g_ncomp[m] <= 1) return;

    __shared__ int par_s[NMAX];
    __shared__ int nroots;
    const int tid = threadIdx.x;

    if (tid == 0) nroots = 0;
    for (int c = tid; c < n; c += 1024) par_s[c] = c;
    __syncthreads();

    // hooking + edge emission
    for (int c = tid; c < n; c += 1024) {
        const unsigned long long key = g_cbest[m][c];
        if (key != KEY_INF) {                       // c is a live root
            const int mn = (int)((key >> 12) & 0xFFF);
            const int mx = (int)(key & 0xFFF);
            const int ru = g_comp[m][mn];
            const int rv = g_comp[m][mx];
            const int t  = (ru == c) ? rv : ru;     // the other root
            const bool mutual = (g_cbest[m][t] == key);
            if (!mutual || c < t) {                 // mutual: smaller emits
                const int e = atomicAdd(&g_ecnt[m], 1);
                if (e < n - 1)                      // hardened: never OOB
                    g_edges[m][e] = make_int2(mn, mx);
            }
            par_s[c] = (mutual && c < t) ? c : t;
        }
    }
    __syncthreads();

    // pointer jumping (12 doublings cover depth 4096)
    #pragma unroll
    for (int p = 0; p < 12; ++p) {
        for (int c = tid; c < n; c += 1024) par_s[c] = par_s[par_s[c]];
        __syncthreads();
    }

    // rewrite comp to final roots
    for (int i = tid; i < n; i += 1024)
        g_comp[m][i] = par_s[g_comp[m][i]];

    // recount live roots; reset cbest for next round
    for (int c = tid; c < n; c += 1024) {
        if (g_cbest[m][c] != KEY_INF && par_s[c] == c) atomicAdd(&nroots, 1);
        g_cbest[m][c] = KEY_INF;
    }
    __syncthreads();
    if (tid == 0) g_ncomp[m] = nroots;
}

// ---------------------------------------------------------------------------
// result = sum_{e in T1}(d1[e]-d2[e])^2 + sum_{e in T2}(d1[e]-d2[e])^2
// ---------------------------------------------------------------------------
__global__ __launch_bounds__(1024, 1)
void finalize_kernel(const float* __restrict__ d1,
                     const float* __restrict__ d2,
                     float* __restrict__ out,
                     int n)
{
    __shared__ float warp_sums[32];
    const int tid = threadIdx.x;

    float acc = 0.0f;
    for (int i = tid; i < n - 1; i += blockDim.x) {
        const int2 e1 = g_edges[0][i];
        const int2 e2 = g_edges[1][i];
        const size_t o1 = (size_t)e1.x * n + e1.y;
        const size_t o2 = (size_t)e2.x * n + e2.y;
        const float a = d1[o1] - d2[o1];
        const float b = d1[o2] - d2[o2];
        acc += a * a + b * b;
    }
    #pragma unroll
    for (int o = 16; o; o >>= 1)
        acc += __shfl_xor_sync(0xffffffffu, acc, o);
    if ((tid & 31) == 0) warp_sums[tid >> 5] = acc;
    __syncthreads();
    if (tid < 32) {
        float v = (tid < (int)(blockDim.x >> 5)) ? warp_sums[tid] : 0.0f;
        #pragma unroll
        for (int o = 16; o; o >>= 1)
            v += __shfl_xor_sync(0xffffffffu, v, o);
        if (tid == 0) out[0] = v;
    }
}

extern "C" void kernel_launch(void* const* d_in, const int* in_sizes, int n_in,
                              void* d_out, int out_size)
{
    const float* d1 = (const float*)d_in[0];
    const float* d2 = (const float*)d_in[1];
    float* out = (float*)d_out;

    const int n = (int)lrint(sqrt((double)in_sizes[0]));   // 4096

    init_kernel<<<dim3((n + 1023) / 1024, 2), 1024>>>(n);

    // Round 0: streaming warp-per-row scan (no component checks needed).
    scan0_kernel<<<dim3(n / 8, 2), 256>>>(d1, d2, n);
    merge_kernel<<<2, 1024>>>(n);

    // Rounds 1..11: cached scans + merges. Components at least halve per
    // round; dead rounds early-exit on g_ncomp.
    for (int r = 1; r < 12; ++r) {
        scan_kernel<<<2 * SB, 256>>>(d1, d2, n);
        merge_kernel<<<2, 1024>>>(n);
    }

    finalize_kernel<<<1, 1024>>>(d1, d2, out, n);
}

// round 17
// speedup vs baseline: 31.1587x; 1.0988x over previous
#include <cuda_runtime.h>
#include <cfloat>
#include <math.h>

#define NMAX 4096
#define SB   128           // cached-scan blocks per matrix (32 vertices each)

// Per-matrix state (m = 0,1)
__device__ int                g_comp [2][NMAX];   // component root per vertex
__device__ unsigned long long g_vbest[2][NMAX];   // cached best outgoing edge key per vertex
__device__ unsigned long long g_cbest[2][NMAX];   // best outgoing edge key per root
__device__ int2               g_edges[2][NMAX];   // MST edges (unordered pairs)
__device__ int                g_ecnt [2];
__device__ int                g_ncomp[2];

// Key layout (56 bits): fp32 bits of d (order-preserving, d >= 0 finite) << 24
//                       | min(i,j) << 12 | max(i,j).
// Order-invariant in (i,j) -> both endpoint components of one physical edge
// compute the IDENTICAL key, so "mutual minimum" == key equality, and keys
// are globally distinct per pair -> cycle-free hooking, unique tie-broken MST.
#define KEY_INF 0xFFFFFFFFFFFFFFFFull

__device__ __forceinline__ unsigned long long pack_key(float w, int i, int j) {
    const unsigned mn = min(i, j), mx = max(i, j);
    return (((unsigned long long)__float_as_uint(w)) << 24)
         | ((unsigned long long)mn << 12) | (unsigned long long)mx;
}

// ---------------------------------------------------------------------------
__global__ void init_kernel(int n)
{
    const int m = blockIdx.y;
    const int i = blockIdx.x * blockDim.x + threadIdx.x;
    if (i < n) {
        g_comp [m][i] = i;
        g_cbest[m][i] = KEY_INF;
        g_vbest[m][i] = KEY_INF;
        g_edges[m][i] = make_int2(0, 0);
    }
    if (i == 0) { g_ecnt[m] = 0; g_ncomp[m] = n; }
}

// ---------------------------------------------------------------------------
// Round 0 scan: every vertex is its own component, so every j != i crosses.
// One WARP per row, streaming; lane-0 writes vbest/cbest directly (root==i).
// grid = (n/8, 2), 256 threads (8 warps/block). Pure 128 MB stream.
// ---------------------------------------------------------------------------
__global__ __launch_bounds__(256, 1)
void scan0_kernel(const float* __restrict__ d1,
                  const float* __restrict__ d2,
                  int n)
{
    const int m = blockIdx.y;
    const float* __restrict__ d = (m == 0) ? d1 : d2;
    const int i    = blockIdx.x * 8 + (threadIdx.x >> 5);   // row
    const int lane = threadIdx.x & 31;

    const float4* __restrict__ row =
        reinterpret_cast<const float4*>(d + (size_t)i * n);
    const int nf4 = n >> 2;

    unsigned long long best = KEY_INF;
    for (int f4 = lane; f4 < nf4; f4 += 32) {
        const float4 w = row[f4];
        const int j0 = f4 << 2;
        if (j0 + 0 != i) best = min(best, pack_key(w.x, i, j0 + 0));
        if (j0 + 1 != i) best = min(best, pack_key(w.y, i, j0 + 1));
        if (j0 + 2 != i) best = min(best, pack_key(w.z, i, j0 + 2));
        if (j0 + 3 != i) best = min(best, pack_key(w.w, i, j0 + 3));
    }
    #pragma unroll
    for (int o = 16; o; o >>= 1)
        best = min(best, __shfl_xor_sync(0xffffffffu, best, o));
    if (lane == 0) {
        g_vbest[m][i] = best;
        g_cbest[m][i] = best;     // comp[i] == i in round 0
    }
}

// ---------------------------------------------------------------------------
// Round 1 scan: after round 0 every vertex merged with its nearest neighbor,
// so (essentially) every cached best is invalid -> unconditional balanced
// full rescan, one WARP per row (same streaming shape as scan0), component
// check against a 16 KB smem copy of comp[]. Unconditional rescan is correct
// regardless: it recomputes the true per-vertex best.
// grid = (n/8, 2), 256 threads.
// ---------------------------------------------------------------------------
__global__ __launch_bounds__(256, 1)
void scan1_kernel(const float* __restrict__ d1,
                  const float* __restrict__ d2,
                  int n)
{
    const int m = blockIdx.y;
    if (g_ncomp[m] <= 1) return;
    const float* __restrict__ d = (m == 0) ? d1 : d2;

    __shared__ __align__(16) int comp_s[NMAX];
    const int tid  = threadIdx.x;
    const int lane = tid & 31;
    const int wid  = tid >> 5;

    for (int k = tid; k < n; k += 256) comp_s[k] = g_comp[m][k];
    __syncthreads();

    const int i  = blockIdx.x * 8 + wid;                    // row
    const int ci = comp_s[i];
    const float4* __restrict__ row =
        reinterpret_cast<const float4*>(d + (size_t)i * n);
    const int4* __restrict__ c4p = reinterpret_cast<const int4*>(comp_s);
    const int nf4 = n >> 2;

    unsigned long long best = KEY_INF;
    for (int f4 = lane; f4 < nf4; f4 += 32) {
        const float4 w = row[f4];
        const int4  cc = c4p[f4];
        const int j0 = f4 << 2;
        if (cc.x != ci) best = min(best, pack_key(w.x, i, j0 + 0));
        if (cc.y != ci) best = min(best, pack_key(w.y, i, j0 + 1));
        if (cc.z != ci) best = min(best, pack_key(w.z, i, j0 + 2));
        if (cc.w != ci) best = min(best, pack_key(w.w, i, j0 + 3));
    }
    #pragma unroll
    for (int o = 16; o; o >>= 1)
        best = min(best, __shfl_xor_sync(0xffffffffu, best, o));
    if (lane == 0) {
        g_vbest[m][i] = best;
        if (best != KEY_INF) atomicMin(&g_cbest[m][ci], best);
    }
}

// ---------------------------------------------------------------------------
// Cached scan (rounds >= 2): cached best stays optimal while its target is
// still external; invalidated vertices are queued and rescanned
// warp-per-vertex. grid = 2*SB blocks, 256 threads; 32 vertices per block.
// ---------------------------------------------------------------------------
__global__ __launch_bounds__(256, 1)
void scan_kernel(const float* __restrict__ d1,
                 const float* __restrict__ d2,
                 int n)
{
    const int m = blockIdx.x & 1;
    if (g_ncomp[m] <= 1) return;
    const float* __restrict__ d = (m == 0) ? d1 : d2;
    const int b = blockIdx.x >> 1;

    __shared__ __align__(16) int comp_s[NMAX];
    __shared__ int queue[NMAX / SB];
    __shared__ int qcnt;

    const int tid  = threadIdx.x;
    const int lane = tid & 31;
    const int wid  = tid >> 5;

    for (int i = tid; i < n; i += 256) comp_s[i] = g_comp[m][i];
    if (tid == 0) qcnt = 0;
    __syncthreads();

    // ---- phase 1: validity check of cached bests; queue invalidated ones ----
    const int vpb = n / SB;                 // 32 vertices per block
    const int v0  = b * vpb;
    for (int i = v0 + tid; i < v0 + vpb; i += 256) {
        bool need = true;
        const unsigned long long key = g_vbest[m][i];
        if (key != KEY_INF) {
            const int mn = (int)((key >> 12) & 0xFFF);
            const int mx = (int)(key & 0xFFF);
            const int t  = (mn == i) ? mx : mn;
            if (comp_s[t] != comp_s[i]) {   // still crossing -> still optimal
                need = false;
                atomicMin(&g_cbest[m][comp_s[i]], key);
            }
        }
        if (need) {
            const int slot = atomicAdd(&qcnt, 1);
            if (slot < vpb) queue[slot] = i;
        }
    }
    __syncthreads();

    // ---- phase 2: warp-per-vertex full-row rescan (8 concurrent rows) ----
    const int nq  = min(qcnt, vpb);
    const int nf4 = n >> 2;
    for (int q = wid; q < nq; q += 8) {
        const int i  = queue[q];
        const int ci = comp_s[i];
        const float4* __restrict__ row =
            reinterpret_cast<const float4*>(d + (size_t)i * n);
        const int4* __restrict__ c4p = reinterpret_cast<const int4*>(comp_s);

        unsigned long long best = KEY_INF;
        for (int f4 = lane; f4 < nf4; f4 += 32) {
            const float4 w = row[f4];
            const int4  cc = c4p[f4];
            const int j0 = f4 << 2;
            if (cc.x != ci) best = min(best, pack_key(w.x, i, j0 + 0));
            if (cc.y != ci) best = min(best, pack_key(w.y, i, j0 + 1));
            if (cc.z != ci) best = min(best, pack_key(w.z, i, j0 + 2));
            if (cc.w != ci) best = min(best, pack_key(w.w, i, j0 + 3));
        }
        #pragma unroll
        for (int o = 16; o; o >>= 1)
            best = min(best, __shfl_xor_sync(0xffffffffu, best, o));
        if (lane == 0) {
            g_vbest[m][i] = best;
            if (best != KEY_INF) atomicMin(&g_cbest[m][ci], best);
        }
    }
}

// ---------------------------------------------------------------------------
// Merge: hooking along min outgoing edges; mutual pairs (key equality) merge
// once with smaller root surviving; smem pointer jumping; comp rewritten;
// components recounted; cbest reset. One block per matrix, 1024 threads.
// ---------------------------------------------------------------------------
__global__ __launch_bounds__(1024, 1)
void merge_kernel(int n)
{
    const int m = blockIdx.x;
    if (g_ncomp[m] <= 1) return;

    __shared__ int par_s[NMAX];
    __shared__ int nroots;
    const int tid = threadIdx.x;

    if (tid == 0) nroots = 0;
    for (int c = tid; c < n; c += 1024) par_s[c] = c;
    __syncthreads();

    // hooking + edge emission
    for (int c = tid; c < n; c += 1024) {
        const unsigned long long key = g_cbest[m][c];
        if (key != KEY_INF) {                       // c is a live root
            const int mn = (int)((key >> 12) & 0xFFF);
            const int mx = (int)(key & 0xFFF);
            const int ru = g_comp[m][mn];
            const int rv = g_comp[m][mx];
            const int t  = (ru == c) ? rv : ru;     // the other root
            const bool mutual = (g_cbest[m][t] == key);
            if (!mutual || c < t) {                 // mutual: smaller emits
                const int e = atomicAdd(&g_ecnt[m], 1);
                if (e < n - 1)                      // hardened: never OOB
                    g_edges[m][e] = make_int2(mn, mx);
            }
            par_s[c] = (mutual && c < t) ? c : t;
        }
    }
    __syncthreads();

    // pointer jumping (12 doublings cover depth 4096)
    #pragma unroll
    for (int p = 0; p < 12; ++p) {
        for (int c = tid; c < n; c += 1024) par_s[c] = par_s[par_s[c]];
        __syncthreads();
    }

    // rewrite comp to final roots
    for (int i = tid; i < n; i += 1024)
        g_comp[m][i] = par_s[g_comp[m][i]];

    // recount live roots; reset cbest for next round
    for (int c = tid; c < n; c += 1024) {
        if (g_cbest[m][c] != KEY_INF && par_s[c] == c) atomicAdd(&nroots, 1);
        g_cbest[m][c] = KEY_INF;
    }
    __syncthreads();
    if (tid == 0) g_ncomp[m] = nroots;
}

// ---------------------------------------------------------------------------
// result = sum_{e in T1}(d1[e]-d2[e])^2 + sum_{e in T2}(d1[e]-d2[e])^2
// ---------------------------------------------------------------------------
__global__ __launch_bounds__(1024, 1)
void finalize_kernel(const float* __restrict__ d1,
                     const float* __restrict__ d2,
                     float* __restrict__ out,
                     int n)
{
    __shared__ float warp_sums[32];
    const int tid = threadIdx.x;

    float acc = 0.0f;
    for (int i = tid; i < n - 1; i += blockDim.x) {
        const int2 e1 = g_edges[0][i];
        const int2 e2 = g_edges[1][i];
        const size_t o1 = (size_t)e1.x * n + e1.y;
        const size_t o2 = (size_t)e2.x * n + e2.y;
        const float a = d1[o1] - d2[o1];
        const float b = d1[o2] - d2[o2];
        acc += a * a + b * b;
    }
    #pragma unroll
    for (int o = 16; o; o >>= 1)
        acc += __shfl_xor_sync(0xffffffffu, acc, o);
    if ((tid & 31) == 0) warp_sums[tid >> 5] = acc;
    __syncthreads();
    if (tid < 32) {
        float v = (tid < (int)(blockDim.x >> 5)) ? warp_sums[tid] : 0.0f;
        #pragma unroll
        for (int o = 16; o; o >>= 1)
            v += __shfl_xor_sync(0xffffffffu, v, o);
        if (tid == 0) out[0] = v;
    }
}

extern "C" void kernel_launch(void* const* d_in, const int* in_sizes, int n_in,
                              void* d_out, int out_size)
{
    const float* d1 = (const float*)d_in[0];
    const float* d2 = (const float*)d_in[1];
    float* out = (float*)d_out;

    const int n = (int)lrint(sqrt((double)in_sizes[0]));   // 4096

    init_kernel<<<dim3((n + 1023) / 1024, 2), 1024>>>(n);

    // Round 0: streaming warp-per-row scan (no component checks needed).
    scan0_kernel<<<dim3(n / 8, 2), 256>>>(d1, d2, n);
    merge_kernel<<<2, 1024>>>(n);

    // Round 1: balanced streaming full rescan (cache is 100% invalid after
    // round 0 — every vertex merged with its nearest neighbor).
    scan1_kernel<<<dim3(n / 8, 2), 256>>>(d1, d2, n);
    merge_kernel<<<2, 1024>>>(n);

    // Rounds 2..11: cached scans + merges; dead rounds early-exit.
    for (int r = 2; r < 12; ++r) {
        scan_kernel<<<2 * SB, 256>>>(d1, d2, n);
        merge_kernel<<<2, 1024>>>(n);
    }

    finalize_kernel<<<1, 1024>>>(d1, d2, out, n);
}